// round 2
// baseline (speedup 1.0000x reference)
#include <cuda_runtime.h>
#include <cstdint>

typedef unsigned long long ULL;

__device__ __forceinline__ ULL pk2(float lo, float hi) {
    ULL r; asm("mov.b64 %0, {%1,%2};" : "=l"(r) : "f"(lo), "f"(hi)); return r;
}
__device__ __forceinline__ void upk2(ULL v, float& lo, float& hi) {
    asm("mov.b64 {%0,%1}, %2;" : "=f"(lo), "=f"(hi) : "l"(v));
}
__device__ __forceinline__ void ffma2(ULL& d, ULL a, ULL b) {
    asm("fma.rn.f32x2 %0, %1, %2, %0;" : "+l"(d) : "l"(a), "l"(b));
}
__device__ __forceinline__ ULL fmul2(ULL a, ULL b) {
    ULL r; asm("mul.rn.f32x2 %0, %1, %2;" : "=l"(r) : "l"(a), "l"(b)); return r;
}

constexpr int Hh = 8, DH = 64, INNER = 512, QLEN = 4096, KLEN = 308, CL = 77;
constexpr int QT = 128, NQT = QLEN / QT;     // 32 query tiles
constexpr int TPB = 256;

constexpr int QS_PAD = 132;                  // QsT[64][132], float4 reads
constexpr int KT_PAD = 313;                  // KT [64][313], scalar reads (odd pad)
constexpr int PS_PAD = 132;                  // PsT[80][132], float4 access
constexpr int OFF_QS = 0;
constexpr int OFF_KT = OFF_QS + 64 * QS_PAD;             // 8448
constexpr int OFF_V  = OFF_KT + 64 * KT_PAD;             // 28480
constexpr int OFF_PS = OFF_V + 80 * 64;                  // 33600
constexpr int SMEM_FLOATS = OFF_PS + 80 * PS_PAD;        // 44160
constexpr size_t SMEM_BYTES = (size_t)SMEM_FLOATS * 4;   // 176640 B

__global__ void __launch_bounds__(TPB, 1)
ddca_kernel(const float* __restrict__ q, const float* __restrict__ k,
            const float* __restrict__ v, const float* __restrict__ dd,
            float* __restrict__ out)
{
    extern __shared__ float sm[];
    float* QsT = sm + OFF_QS;
    float* KT  = sm + OFF_KT;
    float* Vs  = sm + OFF_V;
    float* PsT = sm + OFF_PS;
    __shared__ float wsum[4][8];
    __shared__ float cs[4];

    const int tid = threadIdx.x;
    const int tx = tid & 15;        // key-col group (QK) / dh-col group (PV)
    const int ty = tid >> 4;        // owns query rows 8*ty .. 8*ty+7
    const int wid = tid >> 5, lane = tid & 31;
    const int bid = blockIdx.x;
    const int qt = bid % NQT, bh = bid / NQT, h = bh % Hh, b = bh / Hh;

    const float* qp = q + ((size_t)b * QLEN + (size_t)qt * QT) * INNER + h * DH;
    const float* kp = k + (size_t)b * KLEN * INNER + h * DH;
    const float* vp = v + (size_t)b * KLEN * INNER + h * DH;

    // ---- region scales: cs[r] = (1/8) * 4096 / (4*sum(dd[r])) = 128 / sum ----
    #pragma unroll
    for (int r = 0; r < 4; r++) {
        float s = 0.f;
        #pragma unroll
        for (int i = 0; i < 4; i++) s += dd[r * 1024 + i * 256 + tid];
        #pragma unroll
        for (int o = 16; o > 0; o >>= 1) s += __shfl_xor_sync(0xffffffffu, s, o, 32);
        if (lane == 0) wsum[r][wid] = s;
    }

    // ---- fill QsT: QsT[d][row] (transpose of the 128x64 Q tile) ----
    #pragma unroll
    for (int it = 0; it < 8; it++) {
        int i4 = tid + it * TPB;                 // 2048 = 128 rows * 16 groups
        int row = i4 >> 4, dq = (i4 & 15) * 4;
        float4 t = *reinterpret_cast<const float4*>(qp + (size_t)row * INNER + dq);
        QsT[(dq + 0) * QS_PAD + row] = t.x;
        QsT[(dq + 1) * QS_PAD + row] = t.y;
        QsT[(dq + 2) * QS_PAD + row] = t.z;
        QsT[(dq + 3) * QS_PAD + row] = t.w;
    }
    // ---- fill KT: KT[d][kk] for all 308 keys ----
    for (int i4 = tid; i4 < KLEN * 16; i4 += TPB) {
        int kk = i4 >> 4, dq = (i4 & 15) * 4;
        float4 t = *reinterpret_cast<const float4*>(kp + (size_t)kk * INNER + dq);
        KT[(dq + 0) * KT_PAD + kk] = t.x;
        KT[(dq + 1) * KT_PAD + kk] = t.y;
        KT[(dq + 2) * KT_PAD + kk] = t.z;
        KT[(dq + 3) * KT_PAD + kk] = t.w;
    }
    __syncthreads();
    if (tid < 4) {
        float s = 0.f;
        #pragma unroll
        for (int w = 0; w < 8; w++) s += wsum[tid][w];
        cs[tid] = 128.f / s;
    }
    __syncthreads();

    // ---- per-row region-active bits (2x replication of 32x32 masks) ----
    unsigned mb[8];
    #pragma unroll
    for (int i = 0; i < 8; i++) {
        int qg = qt * QT + ty * 8 + i, y = qg >> 6, x = qg & 63;
        unsigned bits = 0;
        #pragma unroll
        for (int r = 0; r < 4; r++)
            if (dd[r * 1024 + (y >> 1) * 32 + (x >> 1)] > 0.5f) bits |= 1u << r;
        mb[i] = bits;
    }

    float mrow[8], lrow[8];
    ULL o2[4][4];
    #pragma unroll
    for (int i = 0; i < 8; i++) { mrow[i] = -1e30f; lrow[i] = 0.f; }
    #pragma unroll
    for (int p = 0; p < 4; p++)
        #pragma unroll
        for (int j = 0; j < 4; j++) o2[p][j] = 0ull;

    for (int c = 0; c < 4; c++) {
        // -- prefetch this chunk's V (77x64) into registers, hidden by QK --
        float4 vst[5];
        #pragma unroll
        for (int it = 0; it < 5; it++) {
            int i4 = tid + it * TPB;
            if (i4 < CL * 16) {
                int kk = i4 >> 4, dq = (i4 & 15) * 4;
                vst[it] = *reinterpret_cast<const float4*>(
                    vp + (size_t)(c * CL + kk) * INNER + dq);
            }
        }

        // -- S = Q K^T for this chunk: thread has 8 rows x 5 cols --
        ULL acc[4][5];
        #pragma unroll
        for (int p = 0; p < 4; p++)
            #pragma unroll
            for (int j = 0; j < 5; j++) acc[p][j] = 0ull;
        const float* KTc = KT + c * CL + tx;
        const float* Qt  = QsT + 8 * ty;
        #pragma unroll 4
        for (int d = 0; d < 64; d++) {
            float4 qa = *reinterpret_cast<const float4*>(Qt + d * QS_PAD);
            float4 qb = *reinterpret_cast<const float4*>(Qt + d * QS_PAD + 4);
            ULL A0 = pk2(qa.x, qa.y), A1 = pk2(qa.z, qa.w);
            ULL A2 = pk2(qb.x, qb.y), A3 = pk2(qb.z, qb.w);
            #pragma unroll
            for (int j = 0; j < 5; j++) {
                float bv = KTc[d * KT_PAD + 16 * j];
                ULL Bv = pk2(bv, bv);
                ffma2(acc[0][j], A0, Bv); ffma2(acc[1][j], A1, Bv);
                ffma2(acc[2][j], A2, Bv); ffma2(acc[3][j], A3, Bv);
            }
        }

        // -- logits: scale + mask --
        const float cf = cs[c];
        float z[8][5];
        #pragma unroll
        for (int p = 0; p < 4; p++)
            #pragma unroll
            for (int j = 0; j < 5; j++) upk2(acc[p][j], z[2 * p][j], z[2 * p + 1][j]);
        #pragma unroll
        for (int i = 0; i < 8; i++) {
            bool act = (mb[i] >> c) & 1;
            #pragma unroll
            for (int j = 0; j < 5; j++) {
                bool ok = act && (j < 4 || tx < 13);   // local col tx+16j < 77
                z[i][j] = ok ? z[i][j] * cf : -1e30f;
            }
        }

        // -- online softmax: row max over 16 lanes, correction factor --
        float f[8];
        #pragma unroll
        for (int i = 0; i < 8; i++) {
            float mc = z[i][0];
            #pragma unroll
            for (int j = 1; j < 5; j++) mc = fmaxf(mc, z[i][j]);
            #pragma unroll
            for (int o = 8; o > 0; o >>= 1)
                mc = fmaxf(mc, __shfl_xor_sync(0xffffffffu, mc, o, 16));
            float mn = fmaxf(mrow[i], mc);
            f[i] = __expf(mrow[i] - mn);
            mrow[i] = mn;
        }

        // -- exp, stage P transposed (PsT[kk][row]), partial row sums --
        float lc[8];
        #pragma unroll
        for (int i = 0; i < 8; i++) lc[i] = 0.f;
        #pragma unroll
        for (int j = 0; j < 5; j++) {
            float e[8];
            #pragma unroll
            for (int i = 0; i < 8; i++) { e[i] = __expf(z[i][j] - mrow[i]); lc[i] += e[i]; }
            float* pp = PsT + (tx + 16 * j) * PS_PAD + 8 * ty;
            *reinterpret_cast<float4*>(pp)     = make_float4(e[0], e[1], e[2], e[3]);
            *reinterpret_cast<float4*>(pp + 4) = make_float4(e[4], e[5], e[6], e[7]);
        }
        #pragma unroll
        for (int i = 0; i < 8; i++) {
            float s = lc[i];
            #pragma unroll
            for (int o = 8; o > 0; o >>= 1) s += __shfl_xor_sync(0xffffffffu, s, o, 16);
            lrow[i] = lrow[i] * f[i] + s;
        }

        // -- rescale O accumulators --
        #pragma unroll
        for (int p = 0; p < 4; p++) {
            ULL f2 = pk2(f[2 * p], f[2 * p + 1]);
            #pragma unroll
            for (int j = 0; j < 4; j++) o2[p][j] = fmul2(o2[p][j], f2);
        }

        // -- stage V chunk to smem (plain [77][64] layout) --
        #pragma unroll
        for (int it = 0; it < 5; it++) {
            int i4 = tid + it * TPB;
            if (i4 < CL * 16)
                *reinterpret_cast<float4*>(Vs + (size_t)i4 * 4) = vst[it];
        }
        __syncthreads();

        // -- O += P V : thread has 8 rows x 4 dh-cols (cols 4*tx..4*tx+3) --
        const float* Pp  = PsT + 8 * ty;
        const float* Vp4 = Vs + 4 * tx;
        #pragma unroll 7
        for (int kk = 0; kk < CL; kk++) {
            float4 pa = *reinterpret_cast<const float4*>(Pp + kk * PS_PAD);
            float4 pb = *reinterpret_cast<const float4*>(Pp + kk * PS_PAD + 4);
            float4 vv = *reinterpret_cast<const float4*>(Vp4 + kk * 64);
            ULL A0 = pk2(pa.x, pa.y), A1 = pk2(pa.z, pa.w);
            ULL A2 = pk2(pb.x, pb.y), A3 = pk2(pb.z, pb.w);
            ULL B0 = pk2(vv.x, vv.x), B1 = pk2(vv.y, vv.y);
            ULL B2 = pk2(vv.z, vv.z), B3 = pk2(vv.w, vv.w);
            ffma2(o2[0][0], A0, B0); ffma2(o2[0][1], A0, B1);
            ffma2(o2[0][2], A0, B2); ffma2(o2[0][3], A0, B3);
            ffma2(o2[1][0], A1, B0); ffma2(o2[1][1], A1, B1);
            ffma2(o2[1][2], A1, B2); ffma2(o2[1][3], A1, B3);
            ffma2(o2[2][0], A2, B0); ffma2(o2[2][1], A2, B1);
            ffma2(o2[2][2], A2, B2); ffma2(o2[2][3], A2, B3);
            ffma2(o2[3][0], A3, B0); ffma2(o2[3][1], A3, B1);
            ffma2(o2[3][2], A3, B2); ffma2(o2[3][3], A3, B3);
        }
        __syncthreads();
    }

    // ---- epilogue: divide by row sums, write out ----
    float* op = out + ((size_t)b * QLEN + (size_t)qt * QT + 8 * ty) * INNER
              + h * DH + 4 * tx;
    #pragma unroll
    for (int p = 0; p < 4; p++) {
        float r0[4], r1[4];
        #pragma unroll
        for (int j = 0; j < 4; j++) upk2(o2[p][j], r0[j], r1[j]);
        float in0 = 1.f / lrow[2 * p], in1 = 1.f / lrow[2 * p + 1];
        *reinterpret_cast<float4*>(op + (size_t)(2 * p) * INNER) =
            make_float4(r0[0] * in0, r0[1] * in0, r0[2] * in0, r0[3] * in0);
        *reinterpret_cast<float4*>(op + (size_t)(2 * p + 1) * INNER) =
            make_float4(r1[0] * in1, r1[1] * in1, r1[2] * in1, r1[3] * in1);
    }
}

extern "C" void kernel_launch(void* const* d_in, const int* in_sizes, int n_in,
                              void* d_out, int out_size) {
    const float* q  = (const float*)d_in[0];
    const float* k  = (const float*)d_in[1];
    const float* v  = (const float*)d_in[2];
    const float* dd = (const float*)d_in[3];
    float* out = (float*)d_out;

    cudaFuncSetAttribute(ddca_kernel,
                         cudaFuncAttributeMaxDynamicSharedMemorySize,
                         (int)SMEM_BYTES);
    dim3 grid(2 * Hh * NQT);   // 512 CTAs: (b, h, qtile)
    ddca_kernel<<<grid, TPB, SMEM_BYTES>>>(q, k, v, dd, out);
}